// round 6
// baseline (speedup 1.0000x reference)
#include <cuda_runtime.h>

#define B_   64
#define D_   512
#define N_   1200
#define K_   64
#define TN   32
#define NT   38              // ceil(1200/32)
#define NPAD (NT*TN)         // 1216
#define EPSF 1e-12f

// Scratch (static __device__ arrays per harness rules)
__device__ float g_a[B_ * K_ * NPAD];        // a' = softmax * invnorm(x), zero-padded in n
__device__ float g_asum_part[B_ * NT * K_];  // per-tile partial sums of a (unscaled)

typedef unsigned long long u64;

static __device__ __forceinline__ u64 pk(float lo, float hi){
    union { u64 u; float2 f; } t; t.f = make_float2(lo, hi); return t.u;
}
static __device__ __forceinline__ float2 upk(u64 v){
    union { u64 u; float2 f; } t; t.u = v; return t.f;
}
static __device__ __forceinline__ void fma2(u64 &acc, u64 a, u64 b){
    // packed fp32x2 FMA: acc.lo += a.lo*b.lo ; acc.hi += a.hi*b.hi
    asm("fma.rn.f32x2 %0, %1, %2, %0;" : "+l"(acc) : "l"(a), "l"(b));
}

// ---------------------------------------------------------------------------
// KA: per (batch, 32-pixel tile): raw logits GEMM (64k x 32n, D=512 inner),
//     x sumsq -> invnorm, softmax over K, write a' and asum partials.
// ---------------------------------------------------------------------------
__global__ __launch_bounds__(256) void ka_logits(const float* __restrict__ x,
                                                 const float* __restrict__ w)
{
    __shared__ u64 SA[64*65];   // W chunk as duplicated pairs (w,w); later: reduction scratch
    __shared__ u64 SB[64*17];   // x chunk as n-pairs; later: logits tile ls[64][33]

    const int tid  = threadIdx.x;
    const int tile = blockIdx.x;
    const int b    = blockIdx.y;
    const int n0   = tile * TN;
    const int kq   = tid >> 4;   // 0..15 -> k = 4*kq + j
    const int pq   = tid & 15;   // n-pair -> n = 2*pq, 2*pq+1

    u64 acc[4]; acc[0]=acc[1]=acc[2]=acc[3]=0ULL;
    float ps0 = 0.f, ps1 = 0.f;

    const float* xb = x + (size_t)b * D_ * N_;

    for (int c = 0; c < D_; c += 64){
        // stage x pairs: 64 d-rows x 16 pairs, 4 per thread, coalesced float2 LDG
        #pragma unroll
        for (int i = 0; i < 4; ++i){
            int d  = (tid >> 4) + 16*i;
            int p  = tid & 15;
            int gn = n0 + 2*p;
            float2 v = make_float2(0.f, 0.f);
            if (gn < N_) v = *reinterpret_cast<const float2*>(xb + (size_t)(c + d) * N_ + gn);
            SB[d*17 + p] = pk(v.x, v.y);
            ps0 += v.x * v.x; ps1 += v.y * v.y;
        }
        // stage W chunk duplicated: SA[k][dd] = (w,w); 16 per thread, coalesced
        #pragma unroll
        for (int i = 0; i < 16; ++i){
            int e = tid + 256*i;
            int k = e >> 6, dd = e & 63;
            float wv = w[(k << 9) + c + dd];
            SA[k*65 + dd] = pk(wv, wv);
        }
        __syncthreads();
        #pragma unroll 16
        for (int dd = 0; dd < 64; ++dd){
            u64 xp = SB[dd*17 + pq];
            fma2(acc[0], SA[(4*kq+0)*65 + dd], xp);
            fma2(acc[1], SA[(4*kq+1)*65 + dd], xp);
            fma2(acc[2], SA[(4*kq+2)*65 + dd], xp);
            fma2(acc[3], SA[(4*kq+3)*65 + dd], xp);
        }
        __syncthreads();
    }

    // ---- reduce sumsq -> invnorm per pixel ----
    float2* red2 = reinterpret_cast<float2*>(SA);          // 16x16 float2
    float*  sinv = reinterpret_cast<float*>(SA + 256);     // 32 floats
    red2[(tid>>4)*16 + (tid&15)] = make_float2(ps0, ps1);
    __syncthreads();
    if (tid < 16){
        float s0 = 0.f, s1 = 0.f;
        #pragma unroll
        for (int m = 0; m < 16; ++m){ float2 r = red2[m*16 + tid]; s0 += r.x; s1 += r.y; }
        sinv[2*tid]   = 1.f / fmaxf(sqrtf(s0), EPSF);
        sinv[2*tid+1] = 1.f / fmaxf(sqrtf(s1), EPSF);
    }
    __syncthreads();

    // ---- scaled logits into ls[64][33] ----
    float* ls = reinterpret_cast<float*>(SB);
    {
        float i0 = sinv[2*pq], i1 = sinv[2*pq + 1];
        #pragma unroll
        for (int j = 0; j < 4; ++j){
            float2 f = upk(acc[j]);
            ls[(4*kq+j)*33 + 2*pq    ] = f.x * i0;
            ls[(4*kq+j)*33 + 2*pq + 1] = f.y * i1;
        }
    }
    __syncthreads();

    // ---- softmax over K (64) per pixel ----
    float* redm = reinterpret_cast<float*>(SA + 512);  // 8x32
    float* smx  = reinterpret_cast<float*>(SA + 640);  // 32
    float* ssum = reinterpret_cast<float*>(SA + 656);  // 32
    const int w8 = tid >> 5, n = tid & 31;

    float pm = -3.4e38f;
    #pragma unroll
    for (int i = 0; i < 8; ++i) pm = fmaxf(pm, ls[(w8*8 + i)*33 + n]);
    redm[w8*32 + n] = pm;
    __syncthreads();
    if (tid < 32){
        float m = redm[tid];
        #pragma unroll
        for (int i = 1; i < 8; ++i) m = fmaxf(m, redm[i*32 + tid]);
        smx[tid] = m;
    }
    __syncthreads();
    float mval = smx[n];
    float pe = 0.f;
    #pragma unroll
    for (int i = 0; i < 8; ++i){
        int k = w8*8 + i;
        float e = expf(ls[k*33 + n] - mval);
        ls[k*33 + n] = e; pe += e;
    }
    redm[w8*32 + n] = pe;
    __syncthreads();
    if (tid < 32){
        float s = 0.f;
        #pragma unroll
        for (int i = 0; i < 8; ++i) s += redm[i*32 + tid];
        ssum[tid] = 1.f / s;
    }
    __syncthreads();

    // ---- write a' (softmax * invnorm, zero in padding) + asum partials ----
    {
        int  gn    = n0 + n;
        bool valid = gn < N_;
        float coef = ssum[n];
        float invn = sinv[n];
        #pragma unroll
        for (int i = 0; i < 8; ++i){
            int k = w8*8 + i;
            float a  = ls[k*33 + n] * coef;
            float av = valid ? a : 0.f;
            g_a[((size_t)(b*K_ + k))*NPAD + gn] = av * invn;
            float r = av;
            #pragma unroll
            for (int off = 16; off; off >>= 1) r += __shfl_xor_sync(0xffffffffu, r, off);
            if (n == 0) g_asum_part[(b*NT + tile)*K_ + k] = r;
        }
    }
}

// ---------------------------------------------------------------------------
// KB: batched GEMM  vlad_raw[b,k,d] = sum_n a'[b,k,n] * x[b,d,n]
//     CTA = (d-tile 64, batch); full K=64; f32x2 with duplicated x pairs.
// ---------------------------------------------------------------------------
__global__ __launch_bounds__(256) void kb_vlad(const float* __restrict__ x,
                                               float* __restrict__ out)
{
    __shared__ float ast[32*66];   // a' transposed: ast[n][k]
    __shared__ u64   xsd[64*33];   // x duplicated pairs: xsd[d][n] = (x,x)

    const int tid = threadIdx.x;
    const int d0  = blockIdx.x * 64;
    const int b   = blockIdx.y;
    const int kq  = tid >> 4;      // k = 4*kq + {0..3}
    const int dq  = tid & 15;      // d = dq + 16*j

    u64 acc[2][4];
    #pragma unroll
    for (int a = 0; a < 2; ++a)
        #pragma unroll
        for (int j = 0; j < 4; ++j) acc[a][j] = 0ULL;

    const float* xb = x   + (size_t)b * D_ * N_;
    const float* ab = g_a + (size_t)b * K_ * NPAD;

    for (int n0 = 0; n0 < NPAD; n0 += 32){
        #pragma unroll
        for (int i = 0; i < 8; ++i){
            int e = tid + 256*i;
            int k = e >> 5, nn = e & 31;
            ast[nn*66 + k] = ab[(size_t)k*NPAD + n0 + nn];
        }
        #pragma unroll
        for (int i = 0; i < 8; ++i){
            int e = tid + 256*i;
            int d = e >> 5, nn = e & 31;
            int gn = n0 + nn;
            float v = (gn < N_) ? xb[(size_t)(d0 + d)*N_ + gn] : 0.f;
            xsd[d*33 + nn] = pk(v, v);
        }
        __syncthreads();
        #pragma unroll 8
        for (int nn = 0; nn < 32; ++nn){
            u64 ap0 = *reinterpret_cast<const u64*>(&ast[nn*66 + 4*kq]);
            u64 ap1 = *reinterpret_cast<const u64*>(&ast[nn*66 + 4*kq + 2]);
            #pragma unroll
            for (int j = 0; j < 4; ++j){
                u64 xp = xsd[(dq + 16*j)*33 + nn];
                fma2(acc[0][j], ap0, xp);
                fma2(acc[1][j], ap1, xp);
            }
        }
        __syncthreads();
    }

    #pragma unroll
    for (int a2 = 0; a2 < 2; ++a2)
        #pragma unroll
        for (int j = 0; j < 4; ++j){
            float2 f = upk(acc[a2][j]);
            int d = d0 + dq + 16*j;
            out[((size_t)(b*K_ + 4*kq + 2*a2    ))*D_ + d] = f.x;
            out[((size_t)(b*K_ + 4*kq + 2*a2 + 1))*D_ + d] = f.y;
        }
}

// ---------------------------------------------------------------------------
// KC: per (k,b): asum from partials, centroid residual, intra-normalize row.
// ---------------------------------------------------------------------------
__global__ __launch_bounds__(128) void kc_norm(float* __restrict__ out,
                                               const float* __restrict__ cent)
{
    __shared__ float sh[128];
    const int k = blockIdx.x, b = blockIdx.y;
    const int tid = threadIdx.x;

    float s = 0.f;
    for (int t = tid; t < NT; t += 128) s += g_asum_part[(b*NT + t)*K_ + k];
    sh[tid] = s; __syncthreads();
    for (int o = 64; o; o >>= 1){ if (tid < o) sh[tid] += sh[tid + o]; __syncthreads(); }
    float asum = sh[0];
    __syncthreads();

    float*       row  = out  + ((size_t)(b*K_ + k))*D_;
    const float* crow = cent + (size_t)k*D_;
    float v[4]; float sq = 0.f;
    #pragma unroll
    for (int j = 0; j < 4; ++j){
        int d = tid + 128*j;
        v[j] = row[d] - asum * crow[d];
        sq += v[j]*v[j];
    }
    sh[tid] = sq; __syncthreads();
    for (int o = 64; o; o >>= 1){ if (tid < o) sh[tid] += sh[tid + o]; __syncthreads(); }
    float inv = 1.f / fmaxf(sqrtf(sh[0]), EPSF);
    #pragma unroll
    for (int j = 0; j < 4; ++j) row[tid + 128*j] = v[j] * inv;
}

// ---------------------------------------------------------------------------
// KD: per batch: global L2 normalize the 32768-dim vector (in place).
// ---------------------------------------------------------------------------
__global__ __launch_bounds__(256) void kd_gnorm(float* __restrict__ out)
{
    __shared__ float sh[256];
    const int b = blockIdx.x, tid = threadIdx.x;
    float* base = out + (size_t)b * K_ * D_;
    float sq = 0.f;
    for (int i = tid; i < K_*D_; i += 256){ float v = base[i]; sq += v*v; }
    sh[tid] = sq; __syncthreads();
    for (int o = 128; o; o >>= 1){ if (tid < o) sh[tid] += sh[tid + o]; __syncthreads(); }
    float inv = 1.f / fmaxf(sqrtf(sh[0]), EPSF);
    for (int i = tid; i < K_*D_; i += 256) base[i] *= inv;
}

// ---------------------------------------------------------------------------
extern "C" void kernel_launch(void* const* d_in, const int* in_sizes, int n_in,
                              void* d_out, int out_size)
{
    const float* x = (const float*)d_in[0];   // (B, D, H, W)
    const float* w = (const float*)d_in[1];   // (K, D)
    const float* c = (const float*)d_in[2];   // (K, D)
    float* out = (float*)d_out;               // (B, K*D)

    ka_logits<<<dim3(NT, B_), 256>>>(x, w);
    kb_vlad  <<<dim3(D_/64, B_), 256>>>(x, out);
    kc_norm  <<<dim3(K_, B_), 128>>>(out, c);
    kd_gnorm <<<B_, 256>>>(out);
}

// round 8
// speedup vs baseline: 1.3857x; 1.3857x over previous
#include <cuda_runtime.h>

#define B_    64
#define D_    512
#define N_    1200
#define K_    64
#define NT_   5            // number of 256-wide n tiles
#define NTILE 256
#define NPAD  1280         // NT_*NTILE
#define EPSF  1e-12f

// Scratch (static __device__ arrays per harness rules)
__device__ float g_a[B_ * K_ * NPAD];        // a' = softmax * invnorm(x), zero-padded in n
__device__ float g_asum_part[B_ * NT_ * K_]; // per-tile partial sums of a (unscaled)

typedef unsigned long long u64;

static __device__ __forceinline__ u64 pk(float lo, float hi){
    union { u64 u; float2 f; } t; t.f = make_float2(lo, hi); return t.u;
}
static __device__ __forceinline__ float2 upk(u64 v){
    union { u64 u; float2 f; } t; t.u = v; return t.f;
}
static __device__ __forceinline__ void fma2(u64 &acc, u64 a, u64 b){
    // packed fp32x2 FMA: acc.lo += a.lo*b.lo ; acc.hi += a.hi*b.hi
    asm("fma.rn.f32x2 %0, %1, %2, %0;" : "+l"(acc) : "l"(a), "l"(b));
}

// ---------------------------------------------------------------------------
// KA: per (batch, 256-pixel tile): logits GEMM (64k x 256n, D=512),
//     fused sumsq->invnorm, softmax over K, write a' and asum partials.
//     Thread tile 8k x 8n (4 n-pairs). W duplicated in smem, read broadcast.
//     x rows staged at stride 256 floats (1024 B) -> every float4 store is
//     16B-aligned (the R6 stride of 258 trapped on odd rows).
// ---------------------------------------------------------------------------
__global__ __launch_bounds__(256) void ka_logits(const float* __restrict__ x,
                                                 const float* __restrict__ w)
{
    __shared__ __align__(16) float SM[4096 + 2112];
    float*     xs   = SM;                                   // 16 dd x 256 floats
    u64*       ws   = reinterpret_cast<u64*>(SM + 4096);    // 16 dd x 66 dup-pairs
    const u64* xs64 = reinterpret_cast<const u64*>(SM);     // rows of 128 u64

    const int tid  = threadIdx.x;
    const int tile = blockIdx.x;
    const int b    = blockIdx.y;
    const int n0   = tile * NTILE;
    const int kg   = tid >> 5;     // warp id: k-group, 8 k per thread
    const int ng   = tid & 31;     // lane: n-pair base

    u64 acc[8][4];
    #pragma unroll
    for (int i = 0; i < 8; ++i)
        #pragma unroll
        for (int p = 0; p < 4; ++p) acc[i][p] = 0ULL;

    float4 s4 = make_float4(0.f, 0.f, 0.f, 0.f);
    const float* xb = x + (size_t)b * D_ * N_;
    const int n4  = tid & 63;      // x stager: float4 column
    const int rr  = tid >> 6;      // x stager: row group (0..3)
    const int wdd = tid & 15;      // w stager: dd
    const int wkb = tid >> 4;      // w stager: k base

    for (int c = 0; c < D_; c += 16){
        // stage x tile (16 dd x 256 n), accumulate per-pixel sumsq
        #pragma unroll
        for (int it = 0; it < 4; ++it){
            int dd = rr + 4*it;
            int nc = n0 + 4*n4;
            float4 v = make_float4(0.f, 0.f, 0.f, 0.f);
            if (nc < N_) v = *reinterpret_cast<const float4*>(xb + (size_t)(c + dd) * N_ + nc);
            *reinterpret_cast<float4*>(xs + dd*256 + 4*n4) = v;
            s4.x += v.x*v.x; s4.y += v.y*v.y; s4.z += v.z*v.z; s4.w += v.w*v.w;
        }
        // stage W duplicated: ws[dd][k] = (w,w)
        #pragma unroll
        for (int it = 0; it < 4; ++it){
            int k = wkb + 16*it;
            float wv = w[(k << 9) + c + wdd];
            ws[wdd*66 + k] = pk(wv, wv);
        }
        __syncthreads();
        #pragma unroll 4
        for (int dd = 0; dd < 16; ++dd){
            u64 xp[4];
            #pragma unroll
            for (int p = 0; p < 4; ++p) xp[p] = xs64[dd*128 + ng + 32*p];
            const ulonglong2* wr = reinterpret_cast<const ulonglong2*>(ws) + dd*33 + kg*4;
            #pragma unroll
            for (int q = 0; q < 4; ++q){
                ulonglong2 wv = wr[q];   // warp-uniform address -> broadcast LDS.128
                #pragma unroll
                for (int p = 0; p < 4; ++p){
                    fma2(acc[2*q  ][p], wv.x, xp[p]);
                    fma2(acc[2*q+1][p], wv.y, xp[p]);
                }
            }
        }
        __syncthreads();
    }

    // ---- sumsq -> invnorm (smem aliases over xs/ws regions, GEMM is done) ----
    float4* red4 = reinterpret_cast<float4*>(SM);   // 256 float4  (floats [0,1024))
    float*  sinv = SM + 1024;                       // 256 floats  [1024,1280)
    float*  red  = SM + 4096;                       // 2048 floats (ws region)

    red4[rr*64 + n4] = s4;
    __syncthreads();
    if (tid < 64){
        float4 a0 = red4[tid], a1 = red4[64+tid], a2 = red4[128+tid], a3 = red4[192+tid];
        float sx = a0.x+a1.x+a2.x+a3.x;
        float sy = a0.y+a1.y+a2.y+a3.y;
        float sz = a0.z+a1.z+a2.z+a3.z;
        float sw = a0.w+a1.w+a2.w+a3.w;
        int nb = n0 + 4*tid;
        sinv[4*tid+0] = (nb+0 < N_) ? 1.f/fmaxf(sqrtf(sx), EPSF) : 0.f;
        sinv[4*tid+1] = (nb+1 < N_) ? 1.f/fmaxf(sqrtf(sy), EPSF) : 0.f;
        sinv[4*tid+2] = (nb+2 < N_) ? 1.f/fmaxf(sqrtf(sz), EPSF) : 0.f;
        sinv[4*tid+3] = (nb+3 < N_) ? 1.f/fmaxf(sqrtf(sw), EPSF) : 0.f;
    }
    __syncthreads();

    float inv[8];
    #pragma unroll
    for (int p = 0; p < 4; ++p){
        inv[2*p]   = sinv[2*ng + 64*p];
        inv[2*p+1] = sinv[2*ng + 64*p + 1];
    }

    // scale logits by invnorm (in place in acc)
    #pragma unroll
    for (int i = 0; i < 8; ++i)
        #pragma unroll
        for (int p = 0; p < 4; ++p){
            float2 f = upk(acc[i][p]);
            acc[i][p] = pk(f.x * inv[2*p], f.y * inv[2*p+1]);
        }

    // ---- softmax over K=64 per pixel ----
    float M[8];
    #pragma unroll
    for (int p = 0; p < 4; ++p){
        float m0 = -3.4e38f, m1 = -3.4e38f;
        #pragma unroll
        for (int i = 0; i < 8; ++i){
            float2 f = upk(acc[i][p]);
            m0 = fmaxf(m0, f.x); m1 = fmaxf(m1, f.y);
        }
        red[kg*256 + 2*ng + 64*p    ] = m0;
        red[kg*256 + 2*ng + 64*p + 1] = m1;
    }
    __syncthreads();
    #pragma unroll
    for (int j = 0; j < 8; ++j){
        int nl = 2*ng + 64*(j >> 1) + (j & 1);
        float m = red[nl];
        #pragma unroll
        for (int g = 1; g < 8; ++g) m = fmaxf(m, red[g*256 + nl]);
        M[j] = m;
    }
    __syncthreads();

    float ss[8];
    #pragma unroll
    for (int j = 0; j < 8; ++j) ss[j] = 0.f;
    #pragma unroll
    for (int i = 0; i < 8; ++i)
        #pragma unroll
        for (int p = 0; p < 4; ++p){
            float2 f = upk(acc[i][p]);
            float e0 = __expf(f.x - M[2*p]);
            float e1 = __expf(f.y - M[2*p+1]);
            acc[i][p] = pk(e0, e1);
            ss[2*p] += e0; ss[2*p+1] += e1;
        }
    #pragma unroll
    for (int j = 0; j < 8; ++j)
        red[kg*256 + 2*ng + 64*(j >> 1) + (j & 1)] = ss[j];
    __syncthreads();
    float rS[8];
    #pragma unroll
    for (int j = 0; j < 8; ++j){
        int nl = 2*ng + 64*(j >> 1) + (j & 1);
        float s = red[nl];
        #pragma unroll
        for (int g = 1; g < 8; ++g) s += red[g*256 + nl];
        rS[j] = 1.f / s;
    }

    // ---- write a' = a * invnorm (0 in padding) + asum partials ----
    float as_[8];
    #pragma unroll
    for (int i = 0; i < 8; ++i) as_[i] = 0.f;
    float* ga = g_a + ((size_t)(b*K_) + kg*8) * NPAD;
    #pragma unroll
    for (int i = 0; i < 8; ++i){
        #pragma unroll
        for (int p = 0; p < 4; ++p){
            int nl = 2*ng + 64*p;
            int n  = n0 + nl;
            float2 f = upk(acc[i][p]);
            float a0 = f.x * rS[2*p];
            float a1 = f.y * rS[2*p+1];
            if (n >= N_) { a0 = 0.f; a1 = 0.f; }   // N_ even, n even -> joint validity
            as_[i] += a0 + a1;
            *reinterpret_cast<float2*>(ga + (size_t)i*NPAD + n) =
                make_float2(a0 * inv[2*p], a1 * inv[2*p+1]);
        }
    }
    #pragma unroll
    for (int i = 0; i < 8; ++i){
        float r = as_[i];
        #pragma unroll
        for (int off = 16; off; off >>= 1) r += __shfl_xor_sync(0xffffffffu, r, off);
        if (ng == 0) g_asum_part[(b*NT_ + tile)*K_ + kg*8 + i] = r;
    }
}

// ---------------------------------------------------------------------------
// KB: vlad_raw[b,k,d] = sum_n a'[b,k,n] * x[b,d,n]
//     CTA = (128-d tile, batch), 128 threads, thread tile 16k x 4d.
//     a' duplicated in smem, read broadcast; x as natural d-pairs.
// ---------------------------------------------------------------------------
__global__ __launch_bounds__(128) void kb_vlad(const float* __restrict__ x,
                                               float* __restrict__ out)
{
    __shared__ __align__(16) float xsm[32*130];  // [nn][d], rows of 130 floats
    __shared__ __align__(16) u64   adu[32*66];   // [nn][k] duplicated pairs
    const u64* xs64 = reinterpret_cast<const u64*>(xsm);   // rows of 65 u64

    const int tid = threadIdx.x;
    const int d0  = blockIdx.x * 128;
    const int b   = blockIdx.y;
    const int kg  = tid >> 5;     // warp id: 16 k per thread
    const int dg  = tid & 31;     // lane: d-pair base
    const int sg  = tid >> 5, sl = tid & 31;   // stager mapping

    u64 acc[16][2];
    #pragma unroll
    for (int i = 0; i < 16; ++i){ acc[i][0] = 0ULL; acc[i][1] = 0ULL; }

    const float* xb = x   + (size_t)b * D_ * N_;
    const float* ab = g_a + (size_t)b * K_ * NPAD;

    for (int n0 = 0; n0 < NPAD; n0 += 32){
        #pragma unroll
        for (int it = 0; it < 16; ++it){
            int k = sg + 4*it;
            float v = ab[(size_t)k*NPAD + n0 + sl];
            adu[sl*66 + k] = pk(v, v);
        }
        #pragma unroll
        for (int it = 0; it < 32; ++it){
            int d  = sg + 4*it;
            int gn = n0 + sl;
            float v = (gn < N_) ? xb[(size_t)(d0 + d)*N_ + gn] : 0.f;
            xsm[sl*130 + d] = v;
        }
        __syncthreads();
        #pragma unroll 4
        for (int nn = 0; nn < 32; ++nn){
            u64 xp0 = xs64[nn*65 + dg];
            u64 xp1 = xs64[nn*65 + 32 + dg];
            const ulonglong2* ar = reinterpret_cast<const ulonglong2*>(adu) + nn*33 + kg*8;
            #pragma unroll
            for (int q = 0; q < 8; ++q){
                ulonglong2 av = ar[q];   // warp-uniform -> broadcast
                fma2(acc[2*q  ][0], av.x, xp0);
                fma2(acc[2*q  ][1], av.x, xp1);
                fma2(acc[2*q+1][0], av.y, xp0);
                fma2(acc[2*q+1][1], av.y, xp1);
            }
        }
        __syncthreads();
    }

    float* ob = out + ((size_t)(b*K_) + kg*16) * D_ + d0;
    #pragma unroll
    for (int i = 0; i < 16; ++i)
        #pragma unroll
        for (int p = 0; p < 2; ++p){
            float2 f = upk(acc[i][p]);
            *reinterpret_cast<float2*>(ob + (size_t)i*D_ + 2*(dg + 32*p)) = f;
        }
}

// ---------------------------------------------------------------------------
// KC: per (k,b): asum from partials, centroid residual, intra-normalize row,
//     with global L2 norm folded in: rows are unit after intra-norm, so the
//     global norm is exactly sqrt(K)=8 -> multiply by 0.125.
// ---------------------------------------------------------------------------
__global__ __launch_bounds__(128) void kc_norm(float* __restrict__ out,
                                               const float* __restrict__ cent)
{
    __shared__ float sh[128];
    const int k = blockIdx.x, b = blockIdx.y;
    const int tid = threadIdx.x;

    float s = (tid < NT_) ? g_asum_part[(b*NT_ + tid)*K_ + k] : 0.f;
    sh[tid] = s; __syncthreads();
    for (int o = 64; o; o >>= 1){ if (tid < o) sh[tid] += sh[tid + o]; __syncthreads(); }
    float asum = sh[0];
    __syncthreads();

    float*       row  = out  + ((size_t)(b*K_ + k))*D_;
    const float* crow = cent + (size_t)k*D_;
    float v[4]; float sq = 0.f;
    #pragma unroll
    for (int j = 0; j < 4; ++j){
        int d = tid + 128*j;
        v[j] = row[d] - asum * crow[d];
        sq += v[j]*v[j];
    }
    sh[tid] = sq; __syncthreads();
    for (int o = 64; o; o >>= 1){ if (tid < o) sh[tid] += sh[tid + o]; __syncthreads(); }
    float inv = 0.125f / fmaxf(sqrtf(sh[0]), EPSF);
    #pragma unroll
    for (int j = 0; j < 4; ++j) row[tid + 128*j] = v[j] * inv;
}

// ---------------------------------------------------------------------------
extern "C" void kernel_launch(void* const* d_in, const int* in_sizes, int n_in,
                              void* d_out, int out_size)
{
    const float* x = (const float*)d_in[0];   // (B, D, H, W)
    const float* w = (const float*)d_in[1];   // (K, D)
    const float* c = (const float*)d_in[2];   // (K, D)
    float* out = (float*)d_out;               // (B, K*D)

    ka_logits<<<dim3(NT_, B_), 256>>>(x, w);
    kb_vlad  <<<dim3(D_/128, B_), 128>>>(x, out);
    kc_norm  <<<dim3(K_, B_), 128>>>(out, c);
}